// round 2
// baseline (speedup 1.0000x reference)
#include <cuda_runtime.h>
#include <cuda_bf16.h>

// Problem-scale constants (shapes are fixed for this problem instance).
#define NMAX 100000
#define EMAX 800000
#define HDIM 128

// ---------------- static device scratch (no runtime allocation allowed) ----
__device__ float g_bufA[NMAX * HDIM];
__device__ float g_bufB[NMAX * HDIM];
__device__ int   g_count[NMAX];
__device__ int   g_excl[NMAX];
__device__ int   g_rowstart[NMAX + 1];
__device__ int   g_cursor[NMAX];
__device__ int   g_col[EMAX];
__device__ int   g_bsum[128];
__device__ float g_sums[6 * 128];   // [layer][ sum(128) | sumsq(128) ]
__device__ int   g_is64;            // 1 if edge_index is int64, 0 if int32

// ---------------- dtype detection + init -----------------------------------
__global__ void k_init(int n) {
    int i  = blockIdx.x * blockDim.x + threadIdx.x;
    int st = gridDim.x * blockDim.x;
    for (int k = i; k < n; k += st) g_count[k] = 0;
    for (int k = i; k < 6 * 128; k += st) g_sums[k] = 0.f;
    if (i == 0) g_is64 = 1;
}

// If the buffer really holds int64 values in [0, N), every odd 32-bit word
// (the high half, little-endian) is zero. For int32 data those words are live
// edge indices — random in [0, 100000) — so at least one of 4096 is nonzero
// with probability ~1.
__global__ void k_detect(const unsigned* __restrict__ w, int nwords) {
    int i = blockIdx.x * blockDim.x + threadIdx.x;
    int idx = 2 * i + 1;
    if (i < 4096 && idx < nwords) {
        if (w[idx] != 0u) atomicExch(&g_is64, 0);
    }
}

__device__ __forceinline__ int load_idx(const void* ei, long long pos, int is64) {
    if (is64) return (int)((const long long*)ei)[pos];
    return ((const int*)ei)[pos];
}

// ---------------- CSR build ------------------------------------------------
__global__ void k_count(const void* __restrict__ ei, int E, int n) {
    int is64 = g_is64;
    int i  = blockIdx.x * blockDim.x + threadIdx.x;
    int st = gridDim.x * blockDim.x;
    for (int e = i; e < E; e += st) {
        int d = load_idx(ei, e, is64);
        if ((unsigned)d < (unsigned)n) atomicAdd(&g_count[d], 1);
    }
}

// Block-level exclusive scan over 1024 counts per block (256 thr x 4).
__global__ void k_scan1(int n) {
    __shared__ int s[256];
    int tid  = threadIdx.x;
    int base = blockIdx.x * 1024 + tid * 4;
    int v[4];
#pragma unroll
    for (int i = 0; i < 4; i++) v[i] = (base + i < n) ? g_count[base + i] : 0;
    int tsum = v[0] + v[1] + v[2] + v[3];
    s[tid] = tsum;
    __syncthreads();
#pragma unroll
    for (int off = 1; off < 256; off <<= 1) {
        int x = (tid >= off) ? s[tid - off] : 0;
        __syncthreads();
        s[tid] += x;
        __syncthreads();
    }
    int run = s[tid] - tsum;   // exclusive prefix of this thread
#pragma unroll
    for (int i = 0; i < 4; i++) {
        if (base + i < n) g_excl[base + i] = run;
        run += v[i];
    }
    if (tid == 255) g_bsum[blockIdx.x] = s[255];
}

__global__ void k_scan2(int nb) {
    __shared__ int s[128];
    int tid = threadIdx.x;
    int v   = (tid < nb) ? g_bsum[tid] : 0;
    s[tid] = v;
    __syncthreads();
#pragma unroll
    for (int off = 1; off < 128; off <<= 1) {
        int x = (tid >= off) ? s[tid - off] : 0;
        __syncthreads();
        s[tid] += x;
        __syncthreads();
    }
    if (tid < nb) g_bsum[tid] = s[tid] - v;
}

__global__ void k_scan3(int n) {
    int i  = blockIdx.x * blockDim.x + threadIdx.x;
    int st = gridDim.x * blockDim.x;
    for (int k = i; k < n; k += st) {
        int r = g_excl[k] + g_bsum[k >> 10];
        g_rowstart[k] = r;
        g_cursor[k]   = r;
    }
    if (i == 0) {
        // total = excl of last + count of last handled via rowstart[n] below
        g_rowstart[n] = g_excl[n - 1] + g_bsum[(n - 1) >> 10] + g_count[n - 1];
    }
}

__global__ void k_scatter(const void* __restrict__ ei, int E, int n) {
    int is64 = g_is64;
    int i  = blockIdx.x * blockDim.x + threadIdx.x;
    int st = gridDim.x * blockDim.x;
    for (int e = i; e < E; e += st) {
        int d = load_idx(ei, e, is64);
        if ((unsigned)d >= (unsigned)n) continue;      // consistent with k_count
        int s = load_idx(ei, (long long)E + e, is64);
        if ((unsigned)s >= (unsigned)n) s = d;         // defensive clamp
        int p = atomicAdd(&g_cursor[d], 1);
        if ((unsigned)p < (unsigned)EMAX) g_col[p] = s;
    }
}

// ---------------- aggregation: Q[i] = P[i] + sum_{j in adj(i)} P[j] --------
// One warp per node. Lane owns one float4 chunk (32 x float4 = 128 floats).
__global__ void k_aggregate(const float* __restrict__ P, float* __restrict__ Q, int n) {
    int warp = (blockIdx.x * blockDim.x + threadIdx.x) >> 5;
    int lane = threadIdx.x & 31;
    if (warp >= n) return;
    const float4* P4 = (const float4*)P;
    float4 acc = P4[(size_t)warp * 32 + lane];   // self loop
    int s = g_rowstart[warp];
    int t = g_rowstart[warp + 1];
    for (int p = s; p < t; p += 32) {
        int cnt = min(32, t - p);
        int j = (lane < cnt) ? g_col[p + lane] : 0;
        for (int q = 0; q < cnt; q++) {
            int jj = __shfl_sync(0xffffffffu, j, q);
            float4 r = P4[(size_t)jj * 32 + lane];
            acc.x += r.x; acc.y += r.y; acc.z += r.z; acc.w += r.w;
        }
    }
    ((float4*)Q)[(size_t)warp * 32 + lane] = acc;
}

// ---------------- GEMM 128x128 (in-place) + bias + BN partial sums ---------
// Block: 64 rows x 128 cols (full N, full K). 128 threads, 8x8 per thread.
#define SMEM128 ((64 * 132 + 128 * 128) * 4)
__global__ __launch_bounds__(128) void k_gemm128(
    float* __restrict__ A, const float* __restrict__ W,
    const float* __restrict__ bias, float* __restrict__ gsum,
    float* __restrict__ gsq, int n)
{
    extern __shared__ float sm[];
    float* As = sm;              // [64][132] row-major (padded)
    float* Ws = sm + 64 * 132;   // [128][128] W[k][c]
    int tid = threadIdx.x;
    int r0  = blockIdx.x * 64;

    for (int i = tid; i < 2048; i += 128) {           // 64 x 32 float4
        int row = i >> 5, k4 = i & 31;
        float4 v = make_float4(0.f, 0.f, 0.f, 0.f);
        if (r0 + row < n) v = ((const float4*)A)[(size_t)(r0 + row) * 32 + k4];
        float* d = &As[row * 132 + k4 * 4];
        d[0] = v.x; d[1] = v.y; d[2] = v.z; d[3] = v.w;
    }
    for (int i = tid; i < 4096; i += 128)             // 128 x 32 float4
        ((float4*)Ws)[i] = ((const float4*)W)[i];
    __syncthreads();

    int tr = tid >> 4;   // 0..7  -> rows tr*8 .. tr*8+7
    int tc = tid & 15;   // 0..15 -> cols tc*8 .. tc*8+7
    float acc[8][8];
#pragma unroll
    for (int i = 0; i < 8; i++)
#pragma unroll
        for (int j = 0; j < 8; j++) acc[i][j] = 0.f;

    for (int k = 0; k < 128; k += 4) {
        float4 a[8];
#pragma unroll
        for (int i = 0; i < 8; i++) a[i] = *(const float4*)&As[(tr * 8 + i) * 132 + k];
#pragma unroll
        for (int kk = 0; kk < 4; kk++) {
            float4 bA = *(const float4*)&Ws[(k + kk) * 128 + tc * 8];
            float4 bB = *(const float4*)&Ws[(k + kk) * 128 + tc * 8 + 4];
#pragma unroll
            for (int i = 0; i < 8; i++) {
                float av = ((const float*)&a[i])[kk];
                acc[i][0] += av * bA.x; acc[i][1] += av * bA.y;
                acc[i][2] += av * bA.z; acc[i][3] += av * bA.w;
                acc[i][4] += av * bB.x; acc[i][5] += av * bB.y;
                acc[i][6] += av * bB.z; acc[i][7] += av * bB.w;
            }
        }
    }

    float br[8];
#pragma unroll
    for (int j = 0; j < 8; j++) br[j] = bias[tc * 8 + j];
    float ps[8], pq[8];
#pragma unroll
    for (int j = 0; j < 8; j++) { ps[j] = 0.f; pq[j] = 0.f; }
#pragma unroll
    for (int i = 0; i < 8; i++) {
        int row = r0 + tr * 8 + i;
        if (row < n) {
            float y[8];
#pragma unroll
            for (int j = 0; j < 8; j++) {
                y[j] = acc[i][j] + br[j];
                ps[j] += y[j];
                pq[j] += y[j] * y[j];
            }
            float4* dst = (float4*)&A[(size_t)row * 128 + tc * 8];
            dst[0] = make_float4(y[0], y[1], y[2], y[3]);
            dst[1] = make_float4(y[4], y[5], y[6], y[7]);
        }
    }
    __syncthreads();
    float* rs = As;           // reuse smem for reduction
    float* rq = As + 1024;
#pragma unroll
    for (int j = 0; j < 8; j++) {
        rs[tr * 128 + tc * 8 + j] = ps[j];
        rq[tr * 128 + tc * 8 + j] = pq[j];
    }
    __syncthreads();
    if (tr == 0) {
#pragma unroll
        for (int j = 0; j < 8; j++) {
            int c = tc * 8 + j;
            float s = 0.f, q = 0.f;
#pragma unroll
            for (int t = 0; t < 8; t++) { s += rs[t * 128 + c]; q += rq[t * 128 + c]; }
            atomicAdd(&gsum[c], s);
            atomicAdd(&gsq[c], q);
        }
    }
}

// ---------------- BatchNorm (batch stats, biased var) + ReLU, in place -----
__global__ void k_bnrelu(float* __restrict__ Q, const float* __restrict__ gsum,
                         const float* __restrict__ gsq, int n)
{
    __shared__ float s_m[128], s_s[128];
    if (threadIdx.x < 128) {
        float inv_n = 1.0f / (float)n;
        float m = gsum[threadIdx.x] * inv_n;
        float v = gsq[threadIdx.x] * inv_n - m * m;
        s_m[threadIdx.x] = m;
        s_s[threadIdx.x] = rsqrtf(v + 1e-5f);
    }
    __syncthreads();
    int total = n * 32;
    float4* Q4 = (float4*)Q;
    for (int i = blockIdx.x * blockDim.x + threadIdx.x; i < total;
         i += gridDim.x * blockDim.x) {
        float4 v = Q4[i];
        int c = (i & 31) * 4;
        v.x = (v.x - s_m[c + 0]) * s_s[c + 0]; v.x = v.x > 0.f ? v.x : 0.f;
        v.y = (v.y - s_m[c + 1]) * s_s[c + 1]; v.y = v.y > 0.f ? v.y : 0.f;
        v.z = (v.z - s_m[c + 2]) * s_s[c + 2]; v.z = v.z > 0.f ? v.z : 0.f;
        v.w = (v.w - s_m[c + 3]) * s_s[c + 3]; v.w = v.w > 0.f ? v.w : 0.f;
        Q4[i] = v;
    }
}

// ---------------- final GEMM 128 -> 40 + bias ------------------------------
#define SMEM40 ((64 * 132 + 128 * 40) * 4)
__global__ __launch_bounds__(128) void k_gemm40(
    const float* __restrict__ A, const float* __restrict__ W,
    const float* __restrict__ bias, float* __restrict__ out, int n)
{
    extern __shared__ float sm[];
    float* As = sm;             // [64][132]
    float* Ws = sm + 64 * 132;  // [128][40]
    int tid = threadIdx.x;
    int r0  = blockIdx.x * 64;

    for (int i = tid; i < 2048; i += 128) {
        int row = i >> 5, k4 = i & 31;
        float4 v = make_float4(0.f, 0.f, 0.f, 0.f);
        if (r0 + row < n) v = ((const float4*)A)[(size_t)(r0 + row) * 32 + k4];
        float* d = &As[row * 132 + k4 * 4];
        d[0] = v.x; d[1] = v.y; d[2] = v.z; d[3] = v.w;
    }
    for (int i = tid; i < 1280; i += 128)        // 128*40/4
        ((float4*)Ws)[i] = ((const float4*)W)[i];
    __syncthreads();

    int tr = tid >> 3;   // 0..15 -> rows tr*4 .. +3
    int tc = tid & 7;    // 0..7  -> cols tc*5 .. +4
    float acc[4][5];
#pragma unroll
    for (int i = 0; i < 4; i++)
#pragma unroll
        for (int j = 0; j < 5; j++) acc[i][j] = 0.f;

    for (int k = 0; k < 128; k += 4) {
        float4 a[4];
#pragma unroll
        for (int i = 0; i < 4; i++) a[i] = *(const float4*)&As[(tr * 4 + i) * 132 + k];
#pragma unroll
        for (int kk = 0; kk < 4; kk++) {
            float b[5];
#pragma unroll
            for (int j = 0; j < 5; j++) b[j] = Ws[(k + kk) * 40 + tc * 5 + j];
#pragma unroll
            for (int i = 0; i < 4; i++) {
                float av = ((const float*)&a[i])[kk];
#pragma unroll
                for (int j = 0; j < 5; j++) acc[i][j] += av * b[j];
            }
        }
    }
    float br[5];
#pragma unroll
    for (int j = 0; j < 5; j++) br[j] = bias[tc * 5 + j];
#pragma unroll
    for (int i = 0; i < 4; i++) {
        int row = r0 + tr * 4 + i;
        if (row < n) {
#pragma unroll
            for (int j = 0; j < 5; j++)
                out[(size_t)row * 40 + tc * 5 + j] = acc[i][j] + br[j];
        }
    }
}

// ---------------- launcher -------------------------------------------------
extern "C" void kernel_launch(void* const* d_in, const int* in_sizes, int n_in,
                              void* d_out, int out_size)
{
    const float* x  = (const float*)d_in[0];
    const void*  ei = d_in[1];                 // int32 or int64, detected on device
    const float* W0 = (const float*)d_in[2];
    const float* b0 = (const float*)d_in[3];
    const float* W1 = (const float*)d_in[4];
    const float* b1 = (const float*)d_in[5];
    const float* W2 = (const float*)d_in[6];
    const float* b2 = (const float*)d_in[7];
    const float* Wl = (const float*)d_in[8];
    const float* bl = (const float*)d_in[9];
    float* out = (float*)d_out;

    int n = in_sizes[0] / HDIM;
    int E = in_sizes[1] / 2;

    float *bufA, *bufB, *sums;
    cudaGetSymbolAddress((void**)&bufA, g_bufA);
    cudaGetSymbolAddress((void**)&bufB, g_bufB);
    cudaGetSymbolAddress((void**)&sums, g_sums);

    cudaFuncSetAttribute(k_gemm128, cudaFuncAttributeMaxDynamicSharedMemorySize, SMEM128);
    cudaFuncSetAttribute(k_gemm40,  cudaFuncAttributeMaxDynamicSharedMemorySize, SMEM40);

    int nb = (n + 1023) >> 10;

    // CSR build (once per launch; reused by all 3 layers)
    k_init<<<256, 256>>>(n);
    k_detect<<<16, 256>>>((const unsigned*)ei, in_sizes[1]);  // words if int32 view
    k_count<<<(E + 255) / 256, 256>>>(ei, E, n);
    k_scan1<<<nb, 256>>>(n);
    k_scan2<<<1, 128>>>(nb);
    k_scan3<<<(n + 255) / 256, 256>>>(n);
    k_scatter<<<(E + 255) / 256, 256>>>(ei, E, n);

    const float* Ws_[3] = { W0, W1, W2 };
    const float* bs_[3] = { b0, b1, b2 };
    float* bufs[2] = { bufA, bufB };
    const float* P = x;
    for (int l = 0; l < 3; l++) {
        float* Q = bufs[l & 1];
        k_aggregate<<<(n * 32 + 255) / 256, 256>>>(P, Q, n);
        k_gemm128<<<(n + 63) / 64, 128, SMEM128>>>(Q, Ws_[l], bs_[l],
                                                   sums + l * 256, sums + l * 256 + 128, n);
        k_bnrelu<<<(n * 32 + 255) / 256, 256>>>(Q, sums + l * 256, sums + l * 256 + 128, n);
        P = Q;
    }
    k_gemm40<<<(n + 63) / 64, 128, SMEM40>>>(P, Wl, bl, out, n);
}

// round 4
// speedup vs baseline: 1.2179x; 1.2179x over previous
#include <cuda_runtime.h>
#include <cuda_bf16.h>
#include <cstdint>

#define NMAX 100000
#define EMAX 800000
#define HDIM 128

// ---------------- static device scratch ------------------------------------
__device__ float g_bufA[NMAX * HDIM];
__device__ float g_bufB[NMAX * HDIM];
__device__ int   g_count[NMAX];
__device__ int   g_excl[NMAX];
__device__ int   g_rowstart[NMAX + 1];
__device__ int   g_cursor[NMAX];
__device__ int   g_col[EMAX];
__device__ int   g_bsum[128];
__device__ float g_sums[6 * 128];            // [layer][sum(128)|sumsq(128)]
__device__ float g_bnm[3 * 128];             // per-layer mean
__device__ float g_bns[3 * 128];             // per-layer rsqrt(var+eps)
__device__ __nv_bfloat16 g_Whi[3 * 16384];   // row-major [k][n] bf16 hi
__device__ __nv_bfloat16 g_Wlo[3 * 16384];   // row-major [k][n] bf16 lo
__device__ int   g_is64;

// ---------------- helpers ---------------------------------------------------
__device__ __forceinline__ uint32_t smem_u32(const void* p) {
    uint32_t a;
    asm("{ .reg .u64 t; cvta.to.shared.u64 t, %1; cvt.u32.u64 %0, t; }" : "=r"(a) : "l"(p));
    return a;
}
__device__ __forceinline__ void ldsm4(uint32_t* r, uint32_t addr) {
    asm volatile("ldmatrix.sync.aligned.m8n8.x4.shared.b16 {%0,%1,%2,%3}, [%4];"
                 : "=r"(r[0]), "=r"(r[1]), "=r"(r[2]), "=r"(r[3]) : "r"(addr));
}
__device__ __forceinline__ void ldsm2t(uint32_t* r, uint32_t addr) {
    asm volatile("ldmatrix.sync.aligned.m8n8.x2.trans.shared.b16 {%0,%1}, [%2];"
                 : "=r"(r[0]), "=r"(r[1]) : "r"(addr));
}
__device__ __forceinline__ void mma16816(float* d, const uint32_t* a, const uint32_t* b) {
    asm volatile("mma.sync.aligned.m16n8k16.row.col.f32.bf16.bf16.f32 "
                 "{%0,%1,%2,%3}, {%4,%5,%6,%7}, {%8,%9}, {%0,%1,%2,%3};"
                 : "+f"(d[0]), "+f"(d[1]), "+f"(d[2]), "+f"(d[3])
                 : "r"(a[0]), "r"(a[1]), "r"(a[2]), "r"(a[3]), "r"(b[0]), "r"(b[1]));
}

// ---------------- init + dtype detection -----------------------------------
__global__ void k_init(int n) {
    int i  = blockIdx.x * blockDim.x + threadIdx.x;
    int st = gridDim.x * blockDim.x;
    for (int k = i; k < n; k += st) g_count[k] = 0;
    for (int k = i; k < 6 * 128; k += st) g_sums[k] = 0.f;
    if (i == 0) g_is64 = 1;
}
__global__ void k_detect(const unsigned* __restrict__ w, int nwords) {
    int i = blockIdx.x * blockDim.x + threadIdx.x;
    int idx = 2 * i + 1;
    if (i < 4096 && idx < nwords) {
        if (w[idx] != 0u) atomicExch(&g_is64, 0);
    }
}
__device__ __forceinline__ int load_idx(const void* ei, long long pos, int is64) {
    if (is64) return (int)((const long long*)ei)[pos];
    return ((const int*)ei)[pos];
}

// ---------------- CSR build ------------------------------------------------
__global__ void k_count(const void* __restrict__ ei, int E, int n) {
    int is64 = g_is64;
    int i  = blockIdx.x * blockDim.x + threadIdx.x;
    int st = gridDim.x * blockDim.x;
    for (int e = i; e < E; e += st) {
        int d = load_idx(ei, e, is64);
        if ((unsigned)d < (unsigned)n) atomicAdd(&g_count[d], 1);
    }
}
__global__ void k_scan1(int n) {
    __shared__ int s[256];
    int tid  = threadIdx.x;
    int base = blockIdx.x * 1024 + tid * 4;
    int v[4];
#pragma unroll
    for (int i = 0; i < 4; i++) v[i] = (base + i < n) ? g_count[base + i] : 0;
    int tsum = v[0] + v[1] + v[2] + v[3];
    s[tid] = tsum;
    __syncthreads();
#pragma unroll
    for (int off = 1; off < 256; off <<= 1) {
        int x = (tid >= off) ? s[tid - off] : 0;
        __syncthreads();
        s[tid] += x;
        __syncthreads();
    }
    int run = s[tid] - tsum;
#pragma unroll
    for (int i = 0; i < 4; i++) {
        if (base + i < n) g_excl[base + i] = run;
        run += v[i];
    }
    if (tid == 255) g_bsum[blockIdx.x] = s[255];
}
__global__ void k_scan2(int nb) {
    __shared__ int s[128];
    int tid = threadIdx.x;
    int v   = (tid < nb) ? g_bsum[tid] : 0;
    s[tid] = v;
    __syncthreads();
#pragma unroll
    for (int off = 1; off < 128; off <<= 1) {
        int x = (tid >= off) ? s[tid - off] : 0;
        __syncthreads();
        s[tid] += x;
        __syncthreads();
    }
    if (tid < nb) g_bsum[tid] = s[tid] - v;
}
__global__ void k_scan3(int n) {
    int i  = blockIdx.x * blockDim.x + threadIdx.x;
    int st = gridDim.x * blockDim.x;
    for (int k = i; k < n; k += st) {
        int r = g_excl[k] + g_bsum[k >> 10];
        g_rowstart[k] = r;
        g_cursor[k]   = r;
    }
    if (i == 0)
        g_rowstart[n] = g_excl[n - 1] + g_bsum[(n - 1) >> 10] + g_count[n - 1];
}
__global__ void k_scatter(const void* __restrict__ ei, int E, int n) {
    int is64 = g_is64;
    int i  = blockIdx.x * blockDim.x + threadIdx.x;
    int st = gridDim.x * blockDim.x;
    for (int e = i; e < E; e += st) {
        int d = load_idx(ei, e, is64);
        if ((unsigned)d >= (unsigned)n) continue;
        int s = load_idx(ei, (long long)E + e, is64);
        if ((unsigned)s >= (unsigned)n) s = d;
        int p = atomicAdd(&g_cursor[d], 1);
        if ((unsigned)p < (unsigned)EMAX) g_col[p] = s;
    }
}

// ---------------- weight prep: fp32 [k][n] -> row-major bf16 hi/lo ----------
__global__ void k_wprep(const float* __restrict__ W, int l) {
    int idx = blockIdx.x * blockDim.x + threadIdx.x;
    if (idx >= 16384) return;
    float v = W[idx];
    __nv_bfloat16 hi = __float2bfloat16_rn(v);
    __nv_bfloat16 lo = __float2bfloat16_rn(v - __bfloat162float(hi));
    g_Whi[l * 16384 + idx] = hi;
    g_Wlo[l * 16384 + idx] = lo;
}

// ---------------- aggregation (+ fused BN+ReLU of the previous layer) ------
__global__ void k_aggregate(const float* __restrict__ P, float* __restrict__ Q, int n,
                            const float* __restrict__ bnm, const float* __restrict__ bns) {
    int warp = (blockIdx.x * blockDim.x + threadIdx.x) >> 5;
    int lane = threadIdx.x & 31;
    if (warp >= n) return;
    bool dobn = (bnm != nullptr);
    float4 m4 = make_float4(0.f, 0.f, 0.f, 0.f);
    float4 s4 = make_float4(1.f, 1.f, 1.f, 1.f);
    if (dobn) {
        m4 = ((const float4*)bnm)[lane];
        s4 = ((const float4*)bns)[lane];
    }
    const float4* P4 = (const float4*)P;
    float4 acc = P4[(size_t)warp * 32 + lane];
    if (dobn) {
        acc.x = fmaxf((acc.x - m4.x) * s4.x, 0.f);
        acc.y = fmaxf((acc.y - m4.y) * s4.y, 0.f);
        acc.z = fmaxf((acc.z - m4.z) * s4.z, 0.f);
        acc.w = fmaxf((acc.w - m4.w) * s4.w, 0.f);
    }
    int s = g_rowstart[warp];
    int t = g_rowstart[warp + 1];
    for (int p = s; p < t; p += 32) {
        int cnt = min(32, t - p);
        int j = (lane < cnt) ? g_col[p + lane] : 0;
        for (int q = 0; q < cnt; q++) {
            int jj = __shfl_sync(0xffffffffu, j, q);
            float4 r = P4[(size_t)jj * 32 + lane];
            if (dobn) {
                r.x = fmaxf((r.x - m4.x) * s4.x, 0.f);
                r.y = fmaxf((r.y - m4.y) * s4.y, 0.f);
                r.z = fmaxf((r.z - m4.z) * s4.z, 0.f);
                r.w = fmaxf((r.w - m4.w) * s4.w, 0.f);
            }
            acc.x += r.x; acc.y += r.y; acc.z += r.z; acc.w += r.w;
        }
    }
    ((float4*)Q)[(size_t)warp * 32 + lane] = acc;
}

// ---------------- mma.sync bf16 GEMM 128x128 (in place) + bias + BN stats ---
// 3-term bf16 split: D = Ahi*Whi + Alo*Whi + Ahi*Wlo.  256 thr, 8 warps,
// warp = 16 rows x 128 cols.  Smem pitch 136 bf16 (272 B) -> LDSM conflict-free.
#define PA 136
#define TILEB (128 * PA * 2)           // 34816 B per tile
#define OFF_AHI 0
#define OFF_ALO TILEB
#define OFF_WHI (2 * TILEB)
#define OFF_WLO (3 * TILEB)
#define SMEM_MMA (4 * TILEB)           // 139264 B

__global__ __launch_bounds__(256) void k_gemm_mma(
    float* __restrict__ A, const __nv_bfloat16* __restrict__ Whi,
    const __nv_bfloat16* __restrict__ Wlo, const float* __restrict__ bias,
    float* __restrict__ gsum, float* __restrict__ gsq, int n)
{
    extern __shared__ char sm[];
    int tid  = threadIdx.x;
    int lane = tid & 31;
    int warp = tid >> 5;
    int r0g  = blockIdx.x * 128;

    // ---- fill A hi/lo tiles (bf16, pitch 136) ------------------------------
    const float4* A4 = (const float4*)A;
    for (int i = tid; i < 4096; i += 256) {     // row = i>>5, c4 = (i&31)*4
        int row = i >> 5, c4 = (i & 31) * 4;
        float4 v = make_float4(0.f, 0.f, 0.f, 0.f);
        if (r0g + row < n) v = A4[(size_t)(r0g + row) * 32 + (i & 31)];
        __nv_bfloat16 h0 = __float2bfloat16_rn(v.x), h1 = __float2bfloat16_rn(v.y);
        __nv_bfloat16 h2 = __float2bfloat16_rn(v.z), h3 = __float2bfloat16_rn(v.w);
        __nv_bfloat16 l0 = __float2bfloat16_rn(v.x - __bfloat162float(h0));
        __nv_bfloat16 l1 = __float2bfloat16_rn(v.y - __bfloat162float(h1));
        __nv_bfloat16 l2 = __float2bfloat16_rn(v.z - __bfloat162float(h2));
        __nv_bfloat16 l3 = __float2bfloat16_rn(v.w - __bfloat162float(h3));
        uint2 ph = make_uint2(
            (uint32_t)__bfloat16_as_ushort(h0) | ((uint32_t)__bfloat16_as_ushort(h1) << 16),
            (uint32_t)__bfloat16_as_ushort(h2) | ((uint32_t)__bfloat16_as_ushort(h3) << 16));
        uint2 pl = make_uint2(
            (uint32_t)__bfloat16_as_ushort(l0) | ((uint32_t)__bfloat16_as_ushort(l1) << 16),
            (uint32_t)__bfloat16_as_ushort(l2) | ((uint32_t)__bfloat16_as_ushort(l3) << 16));
        *(uint2*)(sm + OFF_AHI + row * (PA * 2) + c4 * 2) = ph;
        *(uint2*)(sm + OFF_ALO + row * (PA * 2) + c4 * 2) = pl;
    }
    // ---- fill W hi/lo tiles ------------------------------------------------
    for (int i = tid; i < 4096; i += 256) {     // k = i>>5, c4 = (i&31)*4
        int k = i >> 5, c4 = (i & 31) * 4;
        uint2 h = *(const uint2*)((const char*)Whi + k * 256 + c4 * 2);
        uint2 l = *(const uint2*)((const char*)Wlo + k * 256 + c4 * 2);
        *(uint2*)(sm + OFF_WHI + k * (PA * 2) + c4 * 2) = h;
        *(uint2*)(sm + OFF_WLO + k * (PA * 2) + c4 * 2) = l;
    }
    __syncthreads();

    // ---- mma mainloop ------------------------------------------------------
    int m  = lane >> 3, ri = lane & 7;       // ldmatrix A addressing
    int rowA = warp * 16 + (m & 1) * 8 + ri;
    uint32_t aHi = smem_u32(sm + OFF_AHI) + rowA * (PA * 2) + (m >> 1) * 16;
    uint32_t aLo = smem_u32(sm + OFF_ALO) + rowA * (PA * 2) + (m >> 1) * 16;
    int l16 = lane & 15;
    int rowB = (l16 >> 3) * 8 + (l16 & 7);   // k-row within chunk
    uint32_t bHi = smem_u32(sm + OFF_WHI) + rowB * (PA * 2);
    uint32_t bLo = smem_u32(sm + OFF_WLO) + rowB * (PA * 2);

    float acc[16][4];
#pragma unroll
    for (int t = 0; t < 16; t++)
#pragma unroll
        for (int j = 0; j < 4; j++) acc[t][j] = 0.f;

#pragma unroll
    for (int kc = 0; kc < 8; kc++) {
        uint32_t ah[4], al[4];
        ldsm4(ah, aHi + kc * 32);
        ldsm4(al, aLo + kc * 32);
        uint32_t kb = kc * 16 * (PA * 2);
#pragma unroll
        for (int nt = 0; nt < 16; nt++) {
            uint32_t bh[2], bl[2];
            ldsm2t(bh, bHi + kb + nt * 16);
            ldsm2t(bl, bLo + kb + nt * 16);
            mma16816(acc[nt], ah, bh);
            mma16816(acc[nt], al, bh);
            mma16816(acc[nt], ah, bl);
        }
    }
    __syncthreads();   // smem tiles dead; reuse for stats

    // ---- epilogue: bias, store, BN partial stats ---------------------------
    float* sred  = (float*)sm;            // [8][128]
    float* sredq = (float*)sm + 1024;     // [8][128]
    int lr = lane >> 2;                   // 0..7
    int lc = lane & 3;
    int row0 = r0g + warp * 16 + lr;
    int row1 = row0 + 8;
    bool v0 = row0 < n, v1 = row1 < n;
#pragma unroll
    for (int nt = 0; nt < 16; nt++) {
        int c0 = nt * 8 + lc * 2;
        float b0v = __ldg(bias + c0), b1v = __ldg(bias + c0 + 1);
        float y00 = acc[nt][0] + b0v, y01 = acc[nt][1] + b1v;
        float y10 = acc[nt][2] + b0v, y11 = acc[nt][3] + b1v;
        if (v0) *(float2*)&A[(size_t)row0 * 128 + c0] = make_float2(y00, y01);
        if (v1) *(float2*)&A[(size_t)row1 * 128 + c0] = make_float2(y10, y11);
        float s0 = (v0 ? y00 : 0.f) + (v1 ? y10 : 0.f);
        float s1 = (v0 ? y01 : 0.f) + (v1 ? y11 : 0.f);
        float q0 = (v0 ? y00 * y00 : 0.f) + (v1 ? y10 * y10 : 0.f);
        float q1 = (v0 ? y01 * y01 : 0.f) + (v1 ? y11 * y11 : 0.f);
#pragma unroll
        for (int o = 4; o < 32; o <<= 1) {
            s0 += __shfl_xor_sync(0xffffffffu, s0, o);
            s1 += __shfl_xor_sync(0xffffffffu, s1, o);
            q0 += __shfl_xor_sync(0xffffffffu, q0, o);
            q1 += __shfl_xor_sync(0xffffffffu, q1, o);
        }
        if (lr == 0) {
            sred [warp * 128 + c0]     = s0;
            sred [warp * 128 + c0 + 1] = s1;
            sredq[warp * 128 + c0]     = q0;
            sredq[warp * 128 + c0 + 1] = q1;
        }
    }
    __syncthreads();
    if (tid < 128) {
        float s = 0.f, q = 0.f;
#pragma unroll
        for (int w = 0; w < 8; w++) {
            s += sred [w * 128 + tid];
            q += sredq[w * 128 + tid];
        }
        atomicAdd(&gsum[tid], s);
        atomicAdd(&gsq[tid], q);
    }
}

// ---------------- BN finalize (per layer, tiny) -----------------------------
__global__ void k_bnfin(int l, int n) {
    int c = threadIdx.x;
    float inv_n = 1.0f / (float)n;
    float m = g_sums[l * 256 + c] * inv_n;
    float v = g_sums[l * 256 + 128 + c] * inv_n - m * m;
    g_bnm[l * 128 + c] = m;
    g_bns[l * 128 + c] = rsqrtf(v + 1e-5f);
}

// ---------------- final GEMM 128 -> 40 + bias (BN+ReLU fused on load) ------
#define SMEM40 ((64 * 132 + 128 * 40) * 4)
__global__ __launch_bounds__(128) void k_gemm40(
    const float* __restrict__ A, const float* __restrict__ W,
    const float* __restrict__ bias, float* __restrict__ out, int n,
    const float* __restrict__ bnm, const float* __restrict__ bns)
{
    extern __shared__ float smf[];
    float* As = smf;             // [64][132]
    float* Ws = smf + 64 * 132;  // [128][40]
    int tid = threadIdx.x;
    int r0  = blockIdx.x * 64;

    for (int i = tid; i < 2048; i += 128) {
        int row = i >> 5, k4 = i & 31;
        float4 v = make_float4(0.f, 0.f, 0.f, 0.f);
        if (r0 + row < n) {
            v = ((const float4*)A)[(size_t)(r0 + row) * 32 + k4];
            float4 m4 = ((const float4*)bnm)[k4];
            float4 s4 = ((const float4*)bns)[k4];
            v.x = fmaxf((v.x - m4.x) * s4.x, 0.f);
            v.y = fmaxf((v.y - m4.y) * s4.y, 0.f);
            v.z = fmaxf((v.z - m4.z) * s4.z, 0.f);
            v.w = fmaxf((v.w - m4.w) * s4.w, 0.f);
        }
        float* d = &As[row * 132 + k4 * 4];
        d[0] = v.x; d[1] = v.y; d[2] = v.z; d[3] = v.w;
    }
    for (int i = tid; i < 1280; i += 128)
        ((float4*)Ws)[i] = ((const float4*)W)[i];
    __syncthreads();

    int tr = tid >> 3;
    int tc = tid & 7;
    float acc[4][5];
#pragma unroll
    for (int i = 0; i < 4; i++)
#pragma unroll
        for (int j = 0; j < 5; j++) acc[i][j] = 0.f;

    for (int k = 0; k < 128; k += 4) {
        float4 a[4];
#pragma unroll
        for (int i = 0; i < 4; i++) a[i] = *(const float4*)&As[(tr * 4 + i) * 132 + k];
#pragma unroll
        for (int kk = 0; kk < 4; kk++) {
            float b[5];
#pragma unroll
            for (int j = 0; j < 5; j++) b[j] = Ws[(k + kk) * 40 + tc * 5 + j];
#pragma unroll
            for (int i = 0; i < 4; i++) {
                float av = ((const float*)&a[i])[kk];
#pragma unroll
                for (int j = 0; j < 5; j++) acc[i][j] += av * b[j];
            }
        }
    }
    float br[5];
#pragma unroll
    for (int j = 0; j < 5; j++) br[j] = bias[tc * 5 + j];
#pragma unroll
    for (int i = 0; i < 4; i++) {
        int row = r0 + tr * 4 + i;
        if (row < n) {
#pragma unroll
            for (int j = 0; j < 5; j++)
                out[(size_t)row * 40 + tc * 5 + j] = acc[i][j] + br[j];
        }
    }
}

// ---------------- launcher -------------------------------------------------
extern "C" void kernel_launch(void* const* d_in, const int* in_sizes, int n_in,
                              void* d_out, int out_size)
{
    const float* x  = (const float*)d_in[0];
    const void*  ei = d_in[1];
    const float* W0 = (const float*)d_in[2];
    const float* b0 = (const float*)d_in[3];
    const float* W1 = (const float*)d_in[4];
    const float* b1 = (const float*)d_in[5];
    const float* W2 = (const float*)d_in[6];
    const float* b2 = (const float*)d_in[7];
    const float* Wl = (const float*)d_in[8];
    const float* bl = (const float*)d_in[9];
    float* out = (float*)d_out;

    int n = in_sizes[0] / HDIM;
    int E = in_sizes[1] / 2;

    float *bufA, *bufB, *sums, *bnm, *bns;
    __nv_bfloat16 *whi, *wlo;
    cudaGetSymbolAddress((void**)&bufA, g_bufA);
    cudaGetSymbolAddress((void**)&bufB, g_bufB);
    cudaGetSymbolAddress((void**)&sums, g_sums);
    cudaGetSymbolAddress((void**)&bnm,  g_bnm);
    cudaGetSymbolAddress((void**)&bns,  g_bns);
    cudaGetSymbolAddress((void**)&whi,  g_Whi);
    cudaGetSymbolAddress((void**)&wlo,  g_Wlo);

    cudaFuncSetAttribute(k_gemm_mma, cudaFuncAttributeMaxDynamicSharedMemorySize, SMEM_MMA);
    cudaFuncSetAttribute(k_gemm40,   cudaFuncAttributeMaxDynamicSharedMemorySize, SMEM40);

    int nb = (n + 1023) >> 10;

    // CSR build (once; reused by all 3 layers)
    k_init<<<256, 256>>>(n);
    k_detect<<<16, 256>>>((const unsigned*)ei, in_sizes[1]);
    k_count<<<(E + 255) / 256, 256>>>(ei, E, n);
    k_scan1<<<nb, 256>>>(n);
    k_scan2<<<1, 128>>>(nb);
    k_scan3<<<(n + 255) / 256, 256>>>(n);
    k_scatter<<<(E + 255) / 256, 256>>>(ei, E, n);

    // weight prep (independent of CSR)
    k_wprep<<<64, 256>>>(W0, 0);
    k_wprep<<<64, 256>>>(W1, 1);
    k_wprep<<<64, 256>>>(W2, 2);

    const float* bs_[3] = { b0, b1, b2 };
    float* bufs[2] = { bufA, bufB };
    const float* P = x;
    int ngrid = (n + 127) / 128;
    for (int l = 0; l < 3; l++) {
        float* Q = bufs[l & 1];
        const float* pm  = (l == 0) ? nullptr : bnm + (l - 1) * 128;
        const float* psd = (l == 0) ? nullptr : bns + (l - 1) * 128;
        k_aggregate<<<(n * 32 + 255) / 256, 256>>>(P, Q, n, pm, psd);
        k_gemm_mma<<<ngrid, 256, SMEM_MMA>>>(Q, whi + l * 16384, wlo + l * 16384,
                                             bs_[l], sums + l * 256,
                                             sums + l * 256 + 128, n);
        k_bnfin<<<1, 128>>>(l, n);
        P = Q;
    }
    k_gemm40<<<(n + 63) / 64, 128, SMEM40>>>(P, Wl, bl, out, n,
                                             bnm + 2 * 128, bns + 2 * 128);
}